// round 10
// baseline (speedup 1.0000x reference)
#include <cuda_runtime.h>
#include <cuda_bf16.h>
#include <math.h>
#include <stdint.h>

// ---------------- problem constants (R1 layout) ----------------
#define TOK   2048
#define HDIM  1024
#define NE    8
#define IDIM  512
#define SIDIM 1024
#define RMAX  4608        // TOK*2 + NE*64 (64-aligned expert segments)

typedef __nv_bfloat16 bf16;

// ---------------- device scratch (identical to R1) ----------------
__device__ int   g_topi[TOK][2];
__device__ float g_topw[TOK][2];
__device__ float g_wsum[NE];
__device__ float g_wmean[NE];
__device__ int   g_cnt[NE];
__device__ int   g_off[NE + 1];
__device__ int   g_fill[NE];
__device__ int   g_pairtok[RMAX];
__device__ int   g_rowexp[RMAX];
__device__ int   g_pairof[TOK][2];
__device__ __align__(16) float g_hbuf[RMAX][IDIM];
__device__ __align__(16) float g_ybuf[RMAX][HDIM];
__device__ __align__(16) float g_hsbuf[TOK][SIDIM];

// ---------------- 1) router (R1 verbatim) ----------------
__global__ __launch_bounds__(256) void router_kernel(const float* __restrict__ x,
                                                     const float* __restrict__ gw,
                                                     const float* __restrict__ lb)
{
    int tid  = threadIdx.x;
    int lane = tid & 31;
    int t    = blockIdx.x * 8 + (tid >> 5);
    if (t >= TOK) return;
    const float* xr = x + (long)t * HDIM;

    float acc[NE];
#pragma unroll
    for (int e = 0; e < NE; e++) acc[e] = 0.f;

    for (int j = lane; j < HDIM; j += 32) {
        float xv = xr[j];
#pragma unroll
        for (int e = 0; e < NE; e++) acc[e] += xv * gw[e * HDIM + j];
    }
#pragma unroll
    for (int e = 0; e < NE; e++) {
#pragma unroll
        for (int o = 16; o > 0; o >>= 1) acc[e] += __shfl_xor_sync(0xffffffffu, acc[e], o);
    }
    if (lane == 0) {
        float sc[NE];
#pragma unroll
        for (int e = 0; e < NE; e++) sc[e] = 1.f / (1.f + expf(-(acc[e] + lb[e])));
        int i0 = 0;
#pragma unroll
        for (int e = 1; e < NE; e++) if (sc[e] > sc[i0]) i0 = e;
        int i1 = -1;
#pragma unroll
        for (int e = 0; e < NE; e++) {
            if (e == i0) continue;
            if (i1 < 0 || sc[e] > sc[i1]) i1 = e;
        }
        float w0 = sc[i0], w1 = sc[i1];
        float s  = w0 + w1 + 1e-8f;
        g_topi[t][0] = i0; g_topi[t][1] = i1;
        g_topw[t][0] = w0 / s; g_topw[t][1] = w1 / s;
    }
}

// ---------------- 2) stats (R1 verbatim) ----------------
__global__ __launch_bounds__(256) void stats_kernel()
{
    int e   = blockIdx.x;
    int tid = threadIdx.x;
    float ws = 0.f;
    int   c  = 0;
    for (int t = tid; t < TOK; t += 256) {
#pragma unroll
        for (int k = 0; k < 2; k++) {
            if (g_topi[t][k] == e) { ws += g_topw[t][k]; c++; }
        }
    }
    __shared__ float sw[256];
    __shared__ int   sc[256];
    sw[tid] = ws; sc[tid] = c;
    __syncthreads();
    for (int s = 128; s > 0; s >>= 1) {
        if (tid < s) { sw[tid] += sw[tid + s]; sc[tid] += sc[tid + s]; }
        __syncthreads();
    }
    if (tid == 0) { g_wsum[e] = sw[0]; g_cnt[e] = sc[0]; }
}

// ---------------- 3) prefix (R1 verbatim) ----------------
__global__ void prefix_kernel()
{
    g_off[0] = 0;
    for (int e = 0; e < NE; e++) {
        int c = g_cnt[e];
        int cm = c > 1 ? c : 1;
        g_wmean[e] = g_wsum[e] / (float)cm;
        g_fill[e]  = 0;
        g_off[e + 1] = g_off[e] + ((c + 63) & ~63);
    }
}

// ---------------- 4) rowmeta (R1 verbatim) ----------------
__global__ __launch_bounds__(256) void rowmeta_kernel()
{
    int r = blockIdx.x * 256 + threadIdx.x;
    if (r >= RMAX) return;
    g_pairtok[r] = -1;
    int e = NE - 1;
#pragma unroll
    for (int i = 0; i < NE; i++) {
        if (r < g_off[i + 1]) { e = i; break; }
    }
    g_rowexp[r] = e;
}

// ---------------- 5) build (R1 verbatim) ----------------
__global__ __launch_bounds__(256) void build_kernel()
{
    int t = blockIdx.x * 256 + threadIdx.x;
    if (t >= TOK) return;
#pragma unroll
    for (int k = 0; k < 2; k++) {
        int e   = g_topi[t][k];
        int pos = atomicAdd(&g_fill[e], 1);
        int r   = g_off[e] + pos;
        g_pairtok[r]  = t;
        g_pairof[t][k] = r;
    }
}

// ---------------- routed gate+up FFMA (R1 verbatim, ROUTED=true only) ----------
template <bool ROUTED>
__global__ __launch_bounds__(256) void gateup_kernel(const float* __restrict__ A,
                                                     const float* __restrict__ Wg,
                                                     const float* __restrict__ Wu)
{
    __shared__ float As[16][68];
    __shared__ float Bg[16][68];
    __shared__ float Bu[16][68];
    __shared__ int   stok[64];

    constexpr int KD  = HDIM;
    constexpr int LDC = ROUTED ? IDIM : SIDIM;
    float* C = ROUTED ? &g_hbuf[0][0] : &g_hsbuf[0][0];

    int tid = threadIdx.x;
    int r0  = blockIdx.y * 64;
    int n0  = blockIdx.x * 64;

    int e = 0;
    if (ROUTED) {
        if (tid < 64) stok[tid] = g_pairtok[r0 + tid];
        __syncthreads();
        if (stok[0] < 0) return;
        e = g_rowexp[r0];
    }
    const float* wg = Wg + (long)e * IDIM * HDIM;
    const float* wu = Wu + (long)e * IDIM * HDIM;

    int lrow = tid >> 2;
    int kq   = (tid & 3) << 2;
    int tx   = tid & 15, ty = tid >> 4;

    float accg[4][4], accu[4][4];
#pragma unroll
    for (int i = 0; i < 4; i++)
#pragma unroll
        for (int j = 0; j < 4; j++) { accg[i][j] = 0.f; accu[i][j] = 0.f; }

    for (int k0 = 0; k0 < KD; k0 += 16) {
        float4 av;
        if (ROUTED) {
            int tk = stok[lrow];
            if (tk >= 0) av = *(const float4*)(A + (long)tk * KD + k0 + kq);
            else         av = make_float4(0.f, 0.f, 0.f, 0.f);
        } else {
            av = *(const float4*)(A + (long)(r0 + lrow) * KD + k0 + kq);
        }
        float4 gv = *(const float4*)(wg + (long)(n0 + lrow) * KD + k0 + kq);
        float4 uv = *(const float4*)(wu + (long)(n0 + lrow) * KD + k0 + kq);
        As[kq + 0][lrow] = av.x; As[kq + 1][lrow] = av.y; As[kq + 2][lrow] = av.z; As[kq + 3][lrow] = av.w;
        Bg[kq + 0][lrow] = gv.x; Bg[kq + 1][lrow] = gv.y; Bg[kq + 2][lrow] = gv.z; Bg[kq + 3][lrow] = gv.w;
        Bu[kq + 0][lrow] = uv.x; Bu[kq + 1][lrow] = uv.y; Bu[kq + 2][lrow] = uv.z; Bu[kq + 3][lrow] = uv.w;
        __syncthreads();
#pragma unroll
        for (int kk = 0; kk < 16; kk++) {
            float4 a4 = *(const float4*)(&As[kk][ty << 2]);
            float4 g4 = *(const float4*)(&Bg[kk][tx << 2]);
            float4 u4 = *(const float4*)(&Bu[kk][tx << 2]);
            float aa[4] = {a4.x, a4.y, a4.z, a4.w};
            float gg[4] = {g4.x, g4.y, g4.z, g4.w};
            float uu[4] = {u4.x, u4.y, u4.z, u4.w};
#pragma unroll
            for (int i = 0; i < 4; i++)
#pragma unroll
                for (int j = 0; j < 4; j++) {
                    accg[i][j] += aa[i] * gg[j];
                    accu[i][j] += aa[i] * uu[j];
                }
        }
        __syncthreads();
    }

#pragma unroll
    for (int i = 0; i < 4; i++) {
        int rlocal = (ty << 2) + i;
        if (ROUTED && stok[rlocal] < 0) continue;
        long r = r0 + rlocal;
#pragma unroll
        for (int j = 0; j < 4; j++) {
            float g  = accg[i][j];
            float sg = 1.f / (1.f + expf(-g));
            C[r * LDC + n0 + (tx << 2) + j] = g * sg * accu[i][j];
        }
    }
}

// ---------------- routed down FFMA (R1 verbatim, ROUTED=true only) -------------
template <bool ROUTED>
__global__ __launch_bounds__(256) void down_kernel(const float* __restrict__ W,
                                                   float* __restrict__ out)
{
    __shared__ float As[16][68];
    __shared__ float Bs[16][68];
    __shared__ int   stok[64];

    constexpr int KD = ROUTED ? IDIM : SIDIM;
    const float* A = ROUTED ? &g_hbuf[0][0] : &g_hsbuf[0][0];
    float*       C = ROUTED ? &g_ybuf[0][0] : out;

    int tid = threadIdx.x;
    int r0  = blockIdx.y * 64;
    int n0  = blockIdx.x * 64;

    int e = 0;
    if (ROUTED) {
        if (tid < 64) stok[tid] = g_pairtok[r0 + tid];
        __syncthreads();
        if (stok[0] < 0) return;
        e = g_rowexp[r0];
    }
    const float* w = W + (long)e * HDIM * IDIM;

    int lrow = tid >> 2;
    int kq   = (tid & 3) << 2;
    int tx   = tid & 15, ty = tid >> 4;

    float acc[4][4];
#pragma unroll
    for (int i = 0; i < 4; i++)
#pragma unroll
        for (int j = 0; j < 4; j++) acc[i][j] = 0.f;

    for (int k0 = 0; k0 < KD; k0 += 16) {
        float4 av = *(const float4*)(A + (long)(r0 + lrow) * KD + k0 + kq);
        float4 bv = *(const float4*)(w + (long)(n0 + lrow) * KD + k0 + kq);
        As[kq + 0][lrow] = av.x; As[kq + 1][lrow] = av.y; As[kq + 2][lrow] = av.z; As[kq + 3][lrow] = av.w;
        Bs[kq + 0][lrow] = bv.x; Bs[kq + 1][lrow] = bv.y; Bs[kq + 2][lrow] = bv.z; Bs[kq + 3][lrow] = bv.w;
        __syncthreads();
#pragma unroll
        for (int kk = 0; kk < 16; kk++) {
            float4 a4 = *(const float4*)(&As[kk][ty << 2]);
            float4 b4 = *(const float4*)(&Bs[kk][tx << 2]);
            float aa[4] = {a4.x, a4.y, a4.z, a4.w};
            float bb[4] = {b4.x, b4.y, b4.z, b4.w};
#pragma unroll
            for (int i = 0; i < 4; i++)
#pragma unroll
                for (int j = 0; j < 4; j++) acc[i][j] += aa[i] * bb[j];
        }
        __syncthreads();
    }

#pragma unroll
    for (int i = 0; i < 4; i++) {
        int rlocal = (ty << 2) + i;
        if (ROUTED && stok[rlocal] < 0) continue;
        long r = r0 + rlocal;
#pragma unroll
        for (int j = 0; j < 4; j++)
            C[r * HDIM + n0 + (tx << 2) + j] = acc[i][j];
    }
}

// ================= NEW: shared-expert mma kernels (static smem) =================
__device__ __forceinline__ uint32_t smem_u32(const void* p) {
    uint32_t a;
    asm("{ .reg .u64 t; cvta.to.shared.u64 t, %1; cvt.u32.u64 %0, t; }" : "=r"(a) : "l"(p));
    return a;
}
__device__ __forceinline__ void ldmx4(uint32_t* r, uint32_t addr) {
    asm volatile("ldmatrix.sync.aligned.m8n8.x4.shared.b16 {%0,%1,%2,%3}, [%4];"
                 : "=r"(r[0]), "=r"(r[1]), "=r"(r[2]), "=r"(r[3]) : "r"(addr));
}
__device__ __forceinline__ void mma16816(float* c, const uint32_t* a, const uint32_t* b) {
    asm volatile("mma.sync.aligned.m16n8k16.row.col.f32.bf16.bf16.f32 "
                 "{%0,%1,%2,%3}, {%4,%5,%6,%7}, {%8,%9}, {%0,%1,%2,%3};"
                 : "+f"(c[0]), "+f"(c[1]), "+f"(c[2]), "+f"(c[3])
                 : "r"(a[0]), "r"(a[1]), "r"(a[2]), "r"(a[3]), "r"(b[0]), "r"(b[1]));
}

#define KF    32
#define SROW  208
#define TILE  (64 * SROW)   // 13312

__device__ __forceinline__ uint32_t pk2(bf16 a, bf16 b) {
    return ((uint32_t)__bfloat16_as_ushort(b) << 16) | (uint32_t)__bfloat16_as_ushort(a);
}
// A rows [hi|lo|hi], B rows [hi|hi|lo]; 32 floats per row per stage
__device__ __forceinline__ void sts_split(char* rowb, int q, float4 v, int bstyle) {
    bf16 h0 = __float2bfloat16_rn(v.x), h1 = __float2bfloat16_rn(v.y);
    bf16 h2 = __float2bfloat16_rn(v.z), h3 = __float2bfloat16_rn(v.w);
    bf16 l0 = __float2bfloat16_rn(v.x - __bfloat162float(h0));
    bf16 l1 = __float2bfloat16_rn(v.y - __bfloat162float(h1));
    bf16 l2 = __float2bfloat16_rn(v.z - __bfloat162float(h2));
    bf16 l3 = __float2bfloat16_rn(v.w - __bfloat162float(h3));
    uint2 H = make_uint2(pk2(h0, h1), pk2(h2, h3));
    uint2 L = make_uint2(pk2(l0, l1), pk2(l2, l3));
    *(uint2*)(rowb + q * 8)       = H;
    *(uint2*)(rowb + 64 + q * 8)  = bstyle ? H : L;
    *(uint2*)(rowb + 128 + q * 8) = bstyle ? L : H;
}

// NB=2: C = silu(A*B0^T) * (A*B1^T);  NB=1: C = A*B0^T. 64x64 tile, K in 32-stages.
template<int NB>
__global__ __launch_bounds__(256) void smma_gemm(const float* __restrict__ A, int lda,
                                                 const float* __restrict__ B0,
                                                 const float* __restrict__ B1,
                                                 float* __restrict__ C, int ldc, int K)
{
    __shared__ char sbuf[(NB + 1) * TILE];   // static: 39936 (NB=2) / 26624 (NB=1)
    int tid = threadIdx.x;
    int n0 = blockIdx.x * 64, r0 = blockIdx.y * 64;

    const float* Bg = B0 + (size_t)n0 * K;
    const float* Bu = (NB == 2) ? (B1 + (size_t)n0 * K) : nullptr;

    int rA[2], qA[2];
#pragma unroll
    for (int i = 0; i < 2; i++) { int idx = tid + i * 256; rA[i] = idx >> 3; qA[i] = idx & 7; }

    float4 ra[2], rb[2], rc[2];
    int S = K / KF;

#pragma unroll
    for (int i = 0; i < 2; i++) {
        int off = qA[i] * 4;
        ra[i] = *(const float4*)(A + (size_t)(r0 + rA[i]) * lda + off);
        rb[i] = *(const float4*)(Bg + (size_t)rA[i] * K + off);
        if (NB == 2) rc[i] = *(const float4*)(Bu + (size_t)rA[i] * K + off);
    }

    int warp = tid >> 5, lane = tid & 31;
    int wm = warp & 3, wn = warp >> 2;

    float acc[NB][4][4];
#pragma unroll
    for (int b = 0; b < NB; b++)
#pragma unroll
        for (int nt = 0; nt < 4; nt++)
#pragma unroll
            for (int j = 0; j < 4; j++) acc[b][nt][j] = 0.f;

    for (int s = 0; s < S; s++) {
#pragma unroll
        for (int i = 0; i < 2; i++) {
            sts_split(sbuf + rA[i] * SROW, qA[i], ra[i], 0);
            sts_split(sbuf + TILE + rA[i] * SROW, qA[i], rb[i], 1);
            if (NB == 2) sts_split(sbuf + 2 * TILE + rA[i] * SROW, qA[i], rc[i], 1);
        }
        __syncthreads();
        if (s + 1 < S) {
#pragma unroll
            for (int i = 0; i < 2; i++) {
                int off = (s + 1) * KF + qA[i] * 4;
                ra[i] = *(const float4*)(A + (size_t)(r0 + rA[i]) * lda + off);
                rb[i] = *(const float4*)(Bg + (size_t)rA[i] * K + off);
                if (NB == 2) rc[i] = *(const float4*)(Bu + (size_t)rA[i] * K + off);
            }
        }
        uint32_t sA = smem_u32(sbuf);
#pragma unroll
        for (int kk = 0; kk < 6; kk++) {
            uint32_t afr[4];
            int mrow = wm * 16 + (lane & 7) + ((lane >> 3) & 1) * 8;
            ldmx4(afr, sA + mrow * SROW + (kk * 16 + (lane >> 4) * 8) * 2);
#pragma unroll
            for (int b = 0; b < NB; b++) {
                uint32_t bs = sA + (1 + b) * TILE;
                uint32_t bfr[4][2];
#pragma unroll
                for (int nb = 0; nb < 2; nb++) {
                    int nrow = wn * 32 + nb * 16 + (lane >> 4) * 8 + (lane & 7);
                    uint32_t r4[4];
                    ldmx4(r4, bs + nrow * SROW + (kk * 16 + ((lane >> 3) & 1) * 8) * 2);
                    bfr[nb * 2][0] = r4[0]; bfr[nb * 2][1] = r4[1];
                    bfr[nb * 2 + 1][0] = r4[2]; bfr[nb * 2 + 1][1] = r4[3];
                }
#pragma unroll
                for (int nt = 0; nt < 4; nt++)
                    mma16816(acc[b][nt], afr, bfr[nt]);
            }
        }
        __syncthreads();
    }

    int rr = wm * 16 + (lane >> 2);
#pragma unroll
    for (int nt = 0; nt < 4; nt++) {
        int col = n0 + wn * 32 + nt * 8 + (lane & 3) * 2;
#pragma unroll
        for (int half = 0; half < 2; half++) {
            int row = r0 + rr + half * 8;
            float o0, o1;
            if (NB == 2) {
                float gg0 = acc[0][nt][2 * half], gg1 = acc[0][nt][2 * half + 1];
                float uu0 = acc[1][nt][2 * half], uu1 = acc[1][nt][2 * half + 1];
                o0 = gg0 * (1.f / (1.f + expf(-gg0))) * uu0;
                o1 = gg1 * (1.f / (1.f + expf(-gg1))) * uu1;
            } else {
                o0 = acc[0][nt][2 * half];
                o1 = acc[0][nt][2 * half + 1];
            }
            *(float2*)(C + (size_t)row * ldc + col) = make_float2(o0, o1);
        }
    }
}

// ---------------- combine (R1 verbatim) ----------------
__global__ __launch_bounds__(256) void combine_kernel(float* __restrict__ out)
{
    int t  = blockIdx.x;
    int p0 = g_pairof[t][0];
    int p1 = g_pairof[t][1];
    float w0 = g_wmean[g_topi[t][0]];
    float w1 = g_wmean[g_topi[t][1]];
    const float* y0 = g_ybuf[p0];
    const float* y1 = g_ybuf[p1];
    float* o = out + (long)t * HDIM;
    for (int h = threadIdx.x; h < HDIM; h += 256)
        o[h] += w0 * y0[h] + w1 * y1[h];
}

// ---------------- launch ----------------
extern "C" void kernel_launch(void* const* d_in, const int* in_sizes, int n_in,
                              void* d_out, int out_size)
{
    (void)in_sizes; (void)n_in; (void)out_size;
    const float* x   = (const float*)d_in[0];
    const float* gw  = (const float*)d_in[1];
    const float* lb  = (const float*)d_in[2];
    const float* egw = (const float*)d_in[3];
    const float* euw = (const float*)d_in[4];
    const float* edw = (const float*)d_in[5];
    const float* sgw = (const float*)d_in[6];
    const float* suw = (const float*)d_in[7];
    const float* sdw = (const float*)d_in[8];
    float* out = (float*)d_out;

    router_kernel<<<TOK / 8, 256>>>(x, gw, lb);
    stats_kernel<<<NE, 256>>>();
    prefix_kernel<<<1, 1>>>();
    rowmeta_kernel<<<(RMAX + 255) / 256, 256>>>();
    build_kernel<<<(TOK + 255) / 256, 256>>>();

    // routed experts: R1-verbatim FFMA path
    gateup_kernel<true><<<dim3(IDIM / 64, RMAX / 64), 256>>>(x, egw, euw);
    down_kernel<true><<<dim3(HDIM / 64, RMAX / 64), 256>>>(edw, nullptr);

    // shared expert: NEW mma path (static smem, no attributes)
    smma_gemm<2><<<dim3(SIDIM / 64, TOK / 64), 256>>>(x, HDIM, sgw, suw,
                                                      &g_hsbuf[0][0], SIDIM, HDIM);
    smma_gemm<1><<<dim3(HDIM / 64, TOK / 64), 256>>>(&g_hsbuf[0][0], SIDIM, sdw, nullptr,
                                                     out, HDIM, SIDIM);

    combine_kernel<<<TOK, 256>>>(out);
}